// round 3
// baseline (speedup 1.0000x reference)
#include <cuda_runtime.h>

#define BB   32
#define C1   64
#define GG   256
#define HW   122
#define W0IN 128
#define CLU  4      // CTAs per cluster (per batch)
#define HCC  16     // hidden channels per scan CTA

typedef unsigned long long u64;

// ---------------- scratch (static __device__: allocation-free) ----------------
__device__ float g_feat[BB * C1 * HW * HW];        // ~122 MB
__device__ float g_i2s[BB * GG * HW * HW];         // ~488 MB (gates incl. both biases)
__device__ float g_h0[BB * C1 * HW];
__device__ float g_h1[BB * C1 * HW];

// ---------------- math helpers ----------------
__device__ __forceinline__ float tanha(float x) {
    float y;
    asm("tanh.approx.f32 %0, %1;" : "=f"(y) : "f"(x));
    return y;
}
__device__ __forceinline__ float sigmf(float x) {
    return 0.5f * tanha(0.5f * x) + 0.5f;
}
__device__ __forceinline__ u64 pk2(float lo, float hi) {
    u64 r;
    asm("mov.b64 %0, {%1, %2};" : "=l"(r) : "f"(lo), "f"(hi));
    return r;
}
__device__ __forceinline__ void fma2(u64& d, u64 a, u64 b) {
    asm("fma.rn.f32x2 %0, %1, %2, %0;" : "+l"(d) : "l"(a), "l"(b));
}
__device__ __forceinline__ void unpk2(u64 v, float& lo, float& hi) {
    asm("mov.b64 {%0, %1}, %2;" : "=f"(lo), "=f"(hi) : "l"(v));
}

// ---------------- conv1: 7x7 valid, [B,1,128,128] -> [B,64,122,122] ----------------
__global__ __launch_bounds__(256) void conv1_kernel(
    const float* __restrict__ x, const float* __restrict__ w1, const float* __restrict__ b1)
{
    __shared__ float xs[7][136];
    __shared__ float ws[C1 * 49];
    __shared__ float bs[C1];

    int bh = blockIdx.x;
    int b = bh / HW, h = bh % HW;
    int t = threadIdx.x;

    for (int i = t; i < C1 * 49; i += 256) ws[i] = w1[i];
    if (t < C1) bs[t] = b1[t];
    for (int i = t; i < 7 * 136; i += 256) {
        int r = i / 136, cw = i % 136;
        xs[r][cw] = (cw < W0IN) ? x[(b * W0IN + (h + r)) * W0IN + cw] : 0.f;
    }
    __syncthreads();

    for (int task = t; task < C1 * 32; task += 256) {
        int c = task >> 5;
        int wt = task & 31;
        int w0 = wt * 4;
        float a0 = 0.f, a1 = 0.f, a2 = 0.f, a3 = 0.f;
#pragma unroll
        for (int kh = 0; kh < 7; kh++) {
            float4 va = *(const float4*)&xs[kh][w0];
            float4 vb = *(const float4*)&xs[kh][w0 + 4];
            float2 vc = *(const float2*)&xs[kh][w0 + 8];
            float f[10] = {va.x, va.y, va.z, va.w, vb.x, vb.y, vb.z, vb.w, vc.x, vc.y};
            const float* wr = &ws[c * 49 + kh * 7];
#pragma unroll
            for (int kw = 0; kw < 7; kw++) {
                float wv = wr[kw];
                a0 += wv * f[kw];
                a1 += wv * f[kw + 1];
                a2 += wv * f[kw + 2];
                a3 += wv * f[kw + 3];
            }
        }
        float bb = bs[c];
        int base = ((b * C1 + c) * HW + h) * HW + w0;
        if (w0 + 0 < HW) g_feat[base + 0] = a0 + bb;
        if (w0 + 1 < HW) g_feat[base + 1] = a1 + bb;
        if (w0 + 2 < HW) g_feat[base + 2] = a2 + bb;
        if (w0 + 3 < HW) g_feat[base + 3] = a3 + bb;
    }
}

// ---------------- i2s: (1,3) conv SAME-width, pre-splatted u64 weights ----------------
// One CTA per (b, h, quarter of 64 output gates).
__global__ __launch_bounds__(256) void i2s_kernel(
    const float* __restrict__ w, const float* __restrict__ bi, const float* __restrict__ bs2)
{
    extern __shared__ float sm[];
    float* fp  = sm;                               // [64][124] padded feat row (+8 slack)
    u64*   wsp = (u64*)(sm + C1 * 124 + 8);        // [64][192] splatted weights (98 KB)
    float* bc  = (float*)(wsp + 64 * 192);         // [64]

    int bx = blockIdx.x;
    int quarter = bx & 3;
    int bh = bx >> 2;
    int b = bh / HW, h = bh % HW;
    int t = threadIdx.x;
    int oc0q = quarter * 64;

    for (int i = t; i < C1 * 124; i += 256) {
        int c = i / 124, cw = i % 124;
        fp[i] = (cw >= 1 && cw <= HW) ? g_feat[((b * C1 + c) * HW + h) * HW + (cw - 1)] : 0.f;
    }
    if (t < 8) fp[C1 * 124 + t] = 0.f;
    for (int i = t; i < 64 * 192; i += 256) {
        float v = w[(oc0q) * 192 + i];
        wsp[i] = pk2(v, v);
    }
    if (t < 64) {
        int og = oc0q + t;
        bc[t] = bi[og] + bs2[og];
    }
    __syncthreads();

    int wt  = t & 31;          // lane = 4-wide w tile
    int rt0 = t >> 5;          // 0..7
    int oc0 = rt0 * 8;         // 8 local oc per thread
    int w0  = wt * 4;
    if (w0 >= HW) return;

    u64 aA[8], aB[8];
#pragma unroll
    for (int i = 0; i < 8; i++) { aA[i] = 0ull; aB[i] = 0ull; }

#pragma unroll 2
    for (int c = 0; c < C1; c++) {
        const float* fr = &fp[c * 124 + w0];
        float4 va = *(const float4*)fr;
        float2 vb = *(const float2*)(fr + 4);
        u64 P0 = pk2(va.x, va.y), P1 = pk2(va.y, va.z), P2 = pk2(va.z, va.w);
        u64 P3 = pk2(va.w, vb.x), P4 = pk2(vb.x, vb.y);
        const u64* wr = &wsp[oc0 * 192 + c * 3];
#pragma unroll
        for (int i = 0; i < 8; i++) {
            u64 s0 = wr[i * 192 + 0];
            u64 s1 = wr[i * 192 + 1];
            u64 s2 = wr[i * 192 + 2];
            fma2(aA[i], s0, P0);  fma2(aB[i], s0, P2);
            fma2(aA[i], s1, P1);  fma2(aB[i], s1, P3);
            fma2(aA[i], s2, P2);  fma2(aB[i], s2, P4);
        }
    }
#pragma unroll
    for (int i = 0; i < 8; i++) {
        int ocl = oc0 + i;
        int og = oc0q + ocl;
        float bb = bc[ocl];
        float r0, r1, r2, r3;
        unpk2(aA[i], r0, r1);
        unpk2(aB[i], r2, r3);
        int base = ((b * GG + og) * HW + h) * HW + w0;
        if (w0 + 0 < HW) g_i2s[base + 0] = r0 + bb;
        if (w0 + 1 < HW) g_i2s[base + 1] = r1 + bb;
        if (w0 + 2 < HW) g_i2s[base + 2] = r2 + bb;
        if (w0 + 3 < HW) g_i2s[base + 3] = r3 + bb;
    }
}

// ---------------- persistent scan: 32 clusters x 4 CTAs x 512 threads ----------------
// CTA = (batch, 16 hidden channels). 1 CTA/SM (128 CTAs). Weights pre-splatted in
// smem; c state in registers; h exchanged via L2 with cluster barriers; i2s gates
// prefetched at row start so DRAM latency overlaps staging + GEMM.
__global__ __launch_bounds__(512, 1) __cluster_dims__(CLU, 1, 1)
void scan_kernel(const float* __restrict__ ws2, float* __restrict__ out)
{
    extern __shared__ float sm[];
    float* hst = sm;                           // [64][124] padded h_prev staging
    u64*   wsp = (u64*)(sm + C1 * 124);        // [4 gates][16 hh][192] splatted (98 KB)

    int t  = threadIdx.x;
    int bx = blockIdx.x;
    int b  = bx / CLU;
    int jr = bx % CLU;
    int hc0 = jr * HCC;

    // resident splatted weights: [gate][hh][192]
    for (int i = t; i < 4 * HCC * 192; i += 512) {
        int row = i / 192, k = i % 192;
        int gate = row >> 4, hh = row & 15;
        float v = ws2[(gate * 64 + hc0 + hh) * 192 + k];
        wsp[i] = pk2(v, v);
    }

    int wid  = t >> 5;               // warp -> hidden channel within CTA (0..15)
    int lane = t & 31;               // lane -> 4-wide w tile
    int hc   = hc0 + wid;
    int w0   = lane * 4;
    bool active = (w0 < HW);

    float cst[4] = {0.f, 0.f, 0.f, 0.f};
    const int HW2 = HW * HW;

    for (int r = 0; r < HW; r++) {
        const float* hsrc = (r & 1) ? g_h1 : g_h0;
        float*       hdst = (r & 1) ? g_h0 : g_h1;

        // --- prefetch i2s gates for this row (independent of h; overlaps staging)
        float pre[16];
        if (active) {
            int gbase = (b * GG) * HW2 + r * HW;
#pragma unroll
            for (int g = 0; g < 4; g++)
#pragma unroll
                for (int j = 0; j < 4; j++) {
                    int wp = w0 + j;
                    pre[g * 4 + j] = (wp < HW)
                        ? __ldcg(&g_i2s[gbase + (g * 64 + hc) * HW2 + wp]) : 0.f;
                }
        }

        // --- stage h_prev (all 64 channels of this batch)
        if (r == 0) {
            for (int i = t; i < C1 * 124; i += 512) hst[i] = 0.f;
        } else {
            for (int i = t; i < C1 * 124; i += 512) {
                int c = i / 124, cw = i % 124;
                float v = 0.f;
                if (cw >= 1 && cw <= HW) v = __ldcg(&hsrc[(b * C1 + c) * HW + (cw - 1)]);
                hst[i] = v;
            }
        }
        __syncthreads();

        if (active) {
            u64 aA[4], aB[4];
#pragma unroll
            for (int g = 0; g < 4; g++) { aA[g] = 0ull; aB[g] = 0ull; }
#pragma unroll 4
            for (int c = 0; c < C1; c++) {
                const float* fr = &hst[c * 124 + w0];
                float4 va = *(const float4*)fr;
                float2 vb = *(const float2*)(fr + 4);
                u64 P0 = pk2(va.x, va.y), P1 = pk2(va.y, va.z), P2 = pk2(va.z, va.w);
                u64 P3 = pk2(va.w, vb.x), P4 = pk2(vb.x, vb.y);
                const u64* wr = &wsp[wid * 192 + c * 3];
#pragma unroll
                for (int g = 0; g < 4; g++) {
                    u64 s0 = wr[g * (HCC * 192) + 0];
                    u64 s1 = wr[g * (HCC * 192) + 1];
                    u64 s2 = wr[g * (HCC * 192) + 2];
                    fma2(aA[g], s0, P0);  fma2(aB[g], s0, P2);
                    fma2(aA[g], s1, P1);  fma2(aB[g], s1, P3);
                    fma2(aA[g], s2, P2);  fma2(aB[g], s2, P4);
                }
            }

            float ga[4][4];
#pragma unroll
            for (int g = 0; g < 4; g++) {
                unpk2(aA[g], ga[g][0], ga[g][1]);
                unpk2(aB[g], ga[g][2], ga[g][3]);
            }

#pragma unroll
            for (int j = 0; j < 4; j++) {
                int wp = w0 + j;
                if (wp >= HW) continue;
                float go = ga[0][j] + pre[0 * 4 + j];
                float gf = ga[1][j] + pre[1 * 4 + j];
                float gi = ga[2][j] + pre[2 * 4 + j];
                float gg = ga[3][j] + pre[3 * 4 + j];

                float cn = sigmf(gf) * cst[j] + sigmf(gi) * tanha(gg);
                float hv = sigmf(go) * tanha(cn);
                cst[j] = cn;
                __stcg(&hdst[(b * C1 + hc) * HW + wp], hv);
                out[((b * C1 + hc) * HW + r) * HW + wp] = hv;
            }
        }

        // release h writes / acquire peers' h for the next row
        asm volatile("barrier.cluster.arrive.aligned;" ::: "memory");
        asm volatile("barrier.cluster.wait.aligned;"   ::: "memory");
    }
}

// ---------------- launch ----------------
extern "C" void kernel_launch(void* const* d_in, const int* in_sizes, int n_in,
                              void* d_out, int out_size)
{
    const float* x   = (const float*)d_in[0];
    const float* c1w = (const float*)d_in[1];
    const float* c1b = (const float*)d_in[2];
    const float* i2w = (const float*)d_in[3];
    const float* i2b = (const float*)d_in[4];
    const float* s2w = (const float*)d_in[5];
    const float* s2b = (const float*)d_in[6];
    float* out = (float*)d_out;

    const int i2s_smem  = (C1 * 124 + 8) * 4 + 64 * 192 * 8 + 64 * 4;     // ~130.4 KB
    const int scan_smem = (C1 * 124) * 4 + 4 * HCC * 192 * 8;             // ~129.8 KB
    cudaFuncSetAttribute(i2s_kernel,  cudaFuncAttributeMaxDynamicSharedMemorySize, i2s_smem);
    cudaFuncSetAttribute(scan_kernel, cudaFuncAttributeMaxDynamicSharedMemorySize, scan_smem);

    conv1_kernel<<<BB * HW, 256>>>(x, c1w, c1b);
    i2s_kernel<<<BB * HW * 4, 256, i2s_smem>>>(i2w, i2b, s2b);
    scan_kernel<<<BB * CLU, 512, scan_smem>>>(s2w, out);
}

// round 5
// speedup vs baseline: 1.1292x; 1.1292x over previous
#include <cuda_runtime.h>

#define BB   32
#define C1   64
#define GG   256
#define HW   122
#define W0IN 128
#define CLU  4      // width slices (CTAs) per batch
#define WSL  31     // nominal slice width (last slice = 29)
#define HSTR 40     // hbuf row stride (floats)

typedef unsigned long long u64;

// ---------------- scratch (static __device__: allocation-free) ----------------
__device__ float g_feat[BB * C1 * HW * HW];        // ~122 MB
__device__ float g_i2s[BB * GG * HW * HW];         // ~488 MB (gates incl. both biases)
__device__ float g_halo[BB][2][CLU][C1];           // per-row boundary columns

// ---------------- math helpers ----------------
__device__ __forceinline__ float tanha(float x) {
    float y;
    asm("tanh.approx.f32 %0, %1;" : "=f"(y) : "f"(x));
    return y;
}
__device__ __forceinline__ float sigmf(float x) {
    return 0.5f * tanha(0.5f * x) + 0.5f;
}
__device__ __forceinline__ u64 pk2(float lo, float hi) {
    u64 r;
    asm("mov.b64 %0, {%1, %2};" : "=l"(r) : "f"(lo), "f"(hi));
    return r;
}
__device__ __forceinline__ void fma2(u64& d, u64 a, u64 b) {
    asm("fma.rn.f32x2 %0, %1, %2, %0;" : "+l"(d) : "l"(a), "l"(b));
}
__device__ __forceinline__ void unpk2(u64 v, float& lo, float& hi) {
    asm("mov.b64 {%0, %1}, %2;" : "=f"(lo), "=f"(hi) : "l"(v));
}

// ---------------- conv1: 7x7 valid, [B,1,128,128] -> [B,64,122,122] ----------------
__global__ __launch_bounds__(256) void conv1_kernel(
    const float* __restrict__ x, const float* __restrict__ w1, const float* __restrict__ b1)
{
    __shared__ float xs[7][136];
    __shared__ float ws[C1 * 49];
    __shared__ float bs[C1];

    int bh = blockIdx.x;
    int b = bh / HW, h = bh % HW;
    int t = threadIdx.x;

    for (int i = t; i < C1 * 49; i += 256) ws[i] = w1[i];
    if (t < C1) bs[t] = b1[t];
    for (int i = t; i < 7 * 136; i += 256) {
        int r = i / 136, cw = i % 136;
        xs[r][cw] = (cw < W0IN) ? x[(b * W0IN + (h + r)) * W0IN + cw] : 0.f;
    }
    __syncthreads();

    for (int task = t; task < C1 * 32; task += 256) {
        int c = task >> 5;
        int wt = task & 31;
        int w0 = wt * 4;
        float a0 = 0.f, a1 = 0.f, a2 = 0.f, a3 = 0.f;
#pragma unroll
        for (int kh = 0; kh < 7; kh++) {
            float4 va = *(const float4*)&xs[kh][w0];
            float4 vb = *(const float4*)&xs[kh][w0 + 4];
            float2 vc = *(const float2*)&xs[kh][w0 + 8];
            float f[10] = {va.x, va.y, va.z, va.w, vb.x, vb.y, vb.z, vb.w, vc.x, vc.y};
            const float* wr = &ws[c * 49 + kh * 7];
#pragma unroll
            for (int kw = 0; kw < 7; kw++) {
                float wv = wr[kw];
                a0 += wv * f[kw];
                a1 += wv * f[kw + 1];
                a2 += wv * f[kw + 2];
                a3 += wv * f[kw + 3];
            }
        }
        float bb = bs[c];
        int base = ((b * C1 + c) * HW + h) * HW + w0;
        if (w0 + 0 < HW) g_feat[base + 0] = a0 + bb;
        if (w0 + 1 < HW) g_feat[base + 1] = a1 + bb;
        if (w0 + 2 < HW) g_feat[base + 2] = a2 + bb;
        if (w0 + 3 < HW) g_feat[base + 3] = a3 + bb;
    }
}

// ---------------- i2s: (1,3) conv SAME-width (R2 version, measured-good) ----------------
__global__ __launch_bounds__(256) void i2s_kernel(
    const float* __restrict__ w, const float* __restrict__ bi, const float* __restrict__ bs2)
{
    extern __shared__ float sm[];
    float* fp = sm;                        // [64][124] padded feat row
    float* ws = sm + C1 * 124 + 8;         // [128][192]
    float* bc = ws + 128 * 192;            // [128]

    int bx = blockIdx.x;
    int half = bx & 1;
    int bh = bx >> 1;
    int b = bh / HW, h = bh % HW;
    int t = threadIdx.x;

    for (int i = t; i < C1 * 124; i += 256) {
        int c = i / 124, cw = i % 124;
        fp[i] = (cw >= 1 && cw <= HW) ? g_feat[((b * C1 + c) * HW + h) * HW + (cw - 1)] : 0.f;
    }
    if (t < 8) fp[C1 * 124 + t] = 0.f;
    for (int i = t; i < 128 * 192; i += 256) ws[i] = w[(half * 128) * 192 + i];
    if (t < 128) {
        int og = half * 128 + t;
        bc[t] = bi[og] + bs2[og];
    }
    __syncthreads();

    int wt = t & 31;
    int rt0 = t >> 5;
    int w0 = wt * 4;
    bool active = (w0 < HW);

    for (int pass = 0; pass < 2; pass++) {
        int oc0 = (rt0 + 8 * pass) * 8;
        if (active) {
            u64 aA[8], aB[8];
#pragma unroll
            for (int i = 0; i < 8; i++) { aA[i] = 0ull; aB[i] = 0ull; }
#pragma unroll 2
            for (int c = 0; c < C1; c++) {
                const float* fr = &fp[c * 124 + w0];
                float4 va = *(const float4*)fr;
                float2 vb = *(const float2*)(fr + 4);
                u64 P0 = pk2(va.x, va.y), P1 = pk2(va.y, va.z), P2 = pk2(va.z, va.w);
                u64 P3 = pk2(va.w, vb.x), P4 = pk2(vb.x, vb.y);
                const float* wr = &ws[oc0 * 192 + c * 3];
#pragma unroll
                for (int i = 0; i < 8; i++) {
                    float wv0 = wr[i * 192 + 0];
                    float wv1 = wr[i * 192 + 1];
                    float wv2 = wr[i * 192 + 2];
                    u64 s0 = pk2(wv0, wv0), s1 = pk2(wv1, wv1), s2 = pk2(wv2, wv2);
                    fma2(aA[i], s0, P0);  fma2(aB[i], s0, P2);
                    fma2(aA[i], s1, P1);  fma2(aB[i], s1, P3);
                    fma2(aA[i], s2, P2);  fma2(aB[i], s2, P4);
                }
            }
#pragma unroll
            for (int i = 0; i < 8; i++) {
                int ocl = oc0 + i;
                int og = half * 128 + ocl;
                float bb = bc[ocl];
                float r0, r1, r2, r3;
                unpk2(aA[i], r0, r1);
                unpk2(aB[i], r2, r3);
                int base = ((b * GG + og) * HW + h) * HW + w0;
                if (w0 + 0 < HW) g_i2s[base + 0] = r0 + bb;
                if (w0 + 1 < HW) g_i2s[base + 1] = r1 + bb;
                if (w0 + 2 < HW) g_i2s[base + 2] = r2 + bb;
                if (w0 + 3 < HW) g_i2s[base + 3] = r3 + bb;
            }
        }
    }
}

// ---------------- persistent scan: width-split, h stays in smem ----------------
// Cluster = batch (4 CTAs, width slices 31/31/31/29). CTA computes all 256 gates
// for its slice; h for the slice lives in a double-buffered smem array; only the
// 64-float boundary columns are exchanged per row via L2 + cluster barrier.
// Thread = (4 channels, 4 gate types, 1 w). Weights transposed [k][gate] in smem
// so f32x2 vectorizes over channel pairs with LDS.128 weight loads.
__global__ __launch_bounds__(512, 1) __cluster_dims__(CLU, 1, 1)
void scan_kernel(const float* __restrict__ ws2, float* __restrict__ out)
{
    extern __shared__ float sm[];
    float* wT   = sm;                         // [192][256]  wT[k][g] = ws2[g][k]
    float* hbuf = sm + 192 * GG;              // [2][64][HSTR]

    int t  = threadIdx.x;
    int bx = blockIdx.x;
    int b  = bx / CLU;
    int jr = bx % CLU;
    int ws_off = jr * WSL;                    // slice start (global w)
    int Ws = (jr == CLU - 1) ? (HW - (CLU - 1) * WSL) : WSL;   // 31/31/31/29

    // transposed weights (one-time)
    for (int i = t; i < 192 * GG; i += 512) {
        int k = i >> 8, g = i & 255;
        wT[i] = ws2[g * 192 + k];
    }
    // zero h buffers
    for (int i = t; i < 2 * C1 * HSTR; i += 512) hbuf[i] = 0.f;
    __syncthreads();

    int wid  = t >> 5;            // warp -> channel group (4 channels)
    int lane = t & 31;            // lane -> local w
    int ch0  = wid * 4;
    int wg   = ws_off + lane;     // global w
    bool active = (lane < Ws);

    float cst[4] = {0.f, 0.f, 0.f, 0.f};
    const int HW2 = HW * HW;

    for (int r = 0; r < HW; r++) {
        int pb = r & 1;           // read buffer (h of row r-1)
        int cb = pb ^ 1;          // write buffer (h of row r)
        const float* hp = hbuf + pb * C1 * HSTR;
        float*       hn = hbuf + cb * C1 * HSTR;

        // ---- prefetch i2s gates for this row (hides DRAM under the GEMM)
        float pre[4][4];
        if (active) {
            int gb = (b * GG) * HW2 + r * HW + wg;
#pragma unroll
            for (int ty = 0; ty < 4; ty++)
#pragma unroll
                for (int cc = 0; cc < 4; cc++)
                    pre[ty][cc] = __ldcg(&g_i2s[gb + (ty * 64 + ch0 + cc) * HW2]);
        }

        // ---- GEMM: gates[ty][ch0..ch0+3] at w = wg
        u64 aA[4], aB[4];         // (ch0,ch0+1) and (ch0+2,ch0+3) per type
#pragma unroll
        for (int ty = 0; ty < 4; ty++) { aA[ty] = 0ull; aB[ty] = 0ull; }

#pragma unroll 4
        for (int c = 0; c < C1; c++) {
            const float* hr = &hp[c * HSTR + lane];   // cols lane..lane+2 = h(wg-1..wg+1)
            float h0 = hr[0], h1 = hr[1], h2 = hr[2];
            u64 s0 = pk2(h0, h0), s1 = pk2(h1, h1), s2 = pk2(h2, h2);
            const float* wk = &wT[(c * 3) * GG + ch0];
#pragma unroll
            for (int ty = 0; ty < 4; ty++) {
                float4 q0 = *(const float4*)(wk + ty * 64);
                float4 q1 = *(const float4*)(wk + ty * 64 + GG);
                float4 q2 = *(const float4*)(wk + ty * 64 + 2 * GG);
                fma2(aA[ty], pk2(q0.x, q0.y), s0);  fma2(aB[ty], pk2(q0.z, q0.w), s0);
                fma2(aA[ty], pk2(q1.x, q1.y), s1);  fma2(aB[ty], pk2(q1.z, q1.w), s1);
                fma2(aA[ty], pk2(q2.x, q2.y), s2);  fma2(aB[ty], pk2(q2.z, q2.w), s2);
            }
        }

        // ---- LSTM epilogue
        if (active) {
            float gate[4][4];
#pragma unroll
            for (int ty = 0; ty < 4; ty++) {
                unpk2(aA[ty], gate[ty][0], gate[ty][1]);
                unpk2(aB[ty], gate[ty][2], gate[ty][3]);
            }
#pragma unroll
            for (int cc = 0; cc < 4; cc++) {
                float go = gate[0][cc] + pre[0][cc];
                float gf = gate[1][cc] + pre[1][cc];
                float gi = gate[2][cc] + pre[2][cc];
                float gg = gate[3][cc] + pre[3][cc];
                float cn = sigmf(gf) * cst[cc] + sigmf(gi) * tanha(gg);
                float hv = sigmf(go) * tanha(cn);
                cst[cc] = cn;
                int ch = ch0 + cc;
                hn[ch * HSTR + lane + 1] = hv;                       // local h
                out[((b * C1 + ch) * HW + r) * HW + wg] = hv;
                if (lane == 0)      __stcg(&g_halo[b][0][jr][ch], hv);   // left edge
                if (lane == Ws - 1) __stcg(&g_halo[b][1][jr][ch], hv);   // right edge
            }
        }

        // ---- release local h + edges; acquire peers' edges
        asm volatile("barrier.cluster.arrive.aligned;" ::: "memory");
        asm volatile("barrier.cluster.wait.aligned;"   ::: "memory");

        // ---- halo fetch into hn cols 0 and Ws+1
        if (t < C1) {
            float v = (jr > 0) ? __ldcg(&g_halo[b][1][jr - 1][t]) : 0.f;
            hn[t * HSTR + 0] = v;
        } else if (t < 2 * C1) {
            int c = t - C1;
            float v = (jr < CLU - 1) ? __ldcg(&g_halo[b][0][jr + 1][c]) : 0.f;
            hn[c * HSTR + Ws + 1] = v;
        }
        __syncthreads();
    }
}

// ---------------- launch ----------------
extern "C" void kernel_launch(void* const* d_in, const int* in_sizes, int n_in,
                              void* d_out, int out_size)
{
    const float* x   = (const float*)d_in[0];
    const float* c1w = (const float*)d_in[1];
    const float* c1b = (const float*)d_in[2];
    const float* i2w = (const float*)d_in[3];
    const float* i2b = (const float*)d_in[4];
    const float* s2w = (const float*)d_in[5];
    const float* s2b = (const float*)d_in[6];
    float* out = (float*)d_out;

    const int i2s_smem  = (C1 * 124 + 8 + 128 * 192 + 128) * sizeof(float);     // ~130.6 KB
    const int scan_smem = (192 * GG + 2 * C1 * HSTR) * sizeof(float);           // ~212 KB
    cudaFuncSetAttribute(i2s_kernel,  cudaFuncAttributeMaxDynamicSharedMemorySize, i2s_smem);
    cudaFuncSetAttribute(scan_kernel, cudaFuncAttributeMaxDynamicSharedMemorySize, scan_smem);

    conv1_kernel<<<BB * HW, 256>>>(x, c1w, c1b);
    i2s_kernel<<<BB * HW * 2, 256, i2s_smem>>>(i2w, i2b, s2b);
    scan_kernel<<<BB * CLU, 512, scan_smem>>>(s2w, out);
}